// round 6
// baseline (speedup 1.0000x reference)
#include <cuda_runtime.h>

// Problem constants (from reference_code)
#define Bn      64
#define h_img   416
#define w_img   416
#define H_out   608
#define W_out   608
#define ROW_OFF 85
#define COL_OFF 80

#define W4     (W_out / 4)    // 152 float4 per output row
#define w4_    (w_img / 4)    // 104 float4 per img row
#define X4_OFF (COL_OFF / 4)  // 20  (aligned: COL_OFF % 4 == 0)
#define HALF   (W4 / 2)       // 76: each thread handles x4 and x4+76

#define PER_B  (H_out * HALF)          // 46208 threads per batch
// Total threads = 64 * 46208 = 2,957,312 = 11552 * 256 exactly.

__global__ void __launch_bounds__(256)
composite_kernel(const float4* __restrict__ img,   // [B,3,h,w] as float4
                 const float4* __restrict__ ref,   // [1,3,H,W] as float4
                 float4* __restrict__ out)         // [B,3,H,W] as float4
{
    const int idx = blockIdx.x * 256 + threadIdx.x;
    const int b   = idx / PER_B;
    const int r   = idx - b * PER_B;
    const int y   = r / HALF;
    const int x0  = r - y * HALF;          // first column; second is x0+76

    const int ry = y - ROW_OFF;
    const bool row_in = (ry >= 0) && (ry < h_img);

    const size_t rrow  = (size_t)y * W4;                             // ref row base
    const size_t ibase = (size_t)b * 3 * h_img * w4_ + (size_t)ry * w4_;
    const size_t obase = (size_t)b * 3 * H_out * W4 + (size_t)y * W4;

    #pragma unroll
    for (int h = 0; h < 2; ++h) {
        const int x4 = x0 + h * HALF;

        // Reference pixels, all 3 channels (4.4 MB tensor -> L2-resident)
        float4 o0 = ref[rrow + (size_t)0 * H_out * W4 + x4];
        float4 o1 = ref[rrow + (size_t)1 * H_out * W4 + x4];
        float4 o2 = ref[rrow + (size_t)2 * H_out * W4 + x4];

        const int rx4 = x4 - X4_OFF;
        if (row_in && rx4 >= 0 && rx4 < w4_) {
            // channel 2 is both mask and payload; stream (read-once)
            const float4 m  = __ldcs(&img[ibase + (size_t)2 * h_img * w4_ + rx4]);
            const float4 i0 = __ldcs(&img[ibase + rx4]);
            const float4 i1 = __ldcs(&img[ibase + (size_t)1 * h_img * w4_ + rx4]);

            if (m.x != 0.0f) { o0.x = i0.x; o1.x = i1.x; o2.x = m.x; }
            if (m.y != 0.0f) { o0.y = i0.y; o1.y = i1.y; o2.y = m.y; }
            if (m.z != 0.0f) { o0.z = i0.z; o1.z = i1.z; o2.z = m.z; }
            if (m.w != 0.0f) { o0.w = i0.w; o1.w = i1.w; o2.w = m.w; }
        }

        __stcs(&out[obase + (size_t)0 * H_out * W4 + x4], o0);   // write-once
        __stcs(&out[obase + (size_t)1 * H_out * W4 + x4], o1);
        __stcs(&out[obase + (size_t)2 * H_out * W4 + x4], o2);
    }
}

extern "C" void kernel_launch(void* const* d_in, const int* in_sizes, int n_in,
                              void* d_out, int out_size)
{
    const float4* img = (const float4*)d_in[0];   // [64,3,416,416] f32
    const float4* ref = (const float4*)d_in[1];   // [1,3,608,608]  f32
    float4* out = (float4*)d_out;                 // [64,3,608,608] f32

    const int blocks = (Bn * PER_B) / 256;        // 11552 exactly
    composite_kernel<<<blocks, 256>>>(img, ref, out);
}